// round 3
// baseline (speedup 1.0000x reference)
#include <cuda_runtime.h>

#define D    128
#define BM   128
#define NMAX 100000

// Scratch (device globals — no runtime allocation allowed).
__device__ float g_hp [(size_t)NMAX * D];
__device__ float g_hpH[(size_t)NMAX * D];

// ---- packed f32x2 helpers (FFMA2 path: 2x fp32 FMA throughput on sm_103a) ----
__device__ __forceinline__ void ffma2(unsigned long long& acc,
                                      unsigned long long a,
                                      unsigned long long b) {
    asm("fma.rn.f32x2 %0, %1, %2, %0;" : "+l"(acc) : "l"(a), "l"(b));
}
__device__ __forceinline__ void fadd2(unsigned long long& a, unsigned long long b) {
    asm("add.rn.f32x2 %0, %0, %1;" : "+l"(a) : "l"(b));
}
__device__ __forceinline__ unsigned long long splat2(float x) {
    unsigned long long r;
    unsigned int xi = __float_as_uint(x);
    asm("mov.b64 %0, {%1, %1};" : "=l"(r) : "r"(xi));
    return r;
}

// Fused node transform: hp = h @ W^T + b ; hpH = hp @ H.
// One 128-row tile per CTA. W (transposed to K-major), H (natural), and the
// row tile all live in 192 KB dynamic smem -> 1 CTA/SM, 256 threads,
// 8x8 micro-tiles packed as f32x2 pairs along the column dimension.
__global__ __launch_bounds__(256, 1)
void node_transform_kernel(const float* __restrict__ h,
                           const float* __restrict__ Ww,
                           const float* __restrict__ Wb,
                           const float* __restrict__ H,
                           int N)
{
    extern __shared__ float sm[];
    float* Ws = sm;             // Ws[k*D + j] = Ww[j*D + k]   (transposed)
    float* Hs = sm + D * D;     // Hs[k*D + j] = H [k*D + j]   (direct)
    float* As = sm + 2 * D * D; // As[i*D + k] : h tile, later hp tile

    const int tid  = threadIdx.x;
    const int row0 = blockIdx.x * BM;

    // --- stage W transposed into smem ---
    {
        int j = tid >> 1, half = tid & 1;
        const float4* Wrow = reinterpret_cast<const float4*>(Ww + j * D);
        #pragma unroll
        for (int u = 0; u < 16; ++u) {
            int k4 = half * 16 + u;
            float4 w = Wrow[k4];
            int k = k4 * 4;
            Ws[(k + 0) * D + j] = w.x;
            Ws[(k + 1) * D + j] = w.y;
            Ws[(k + 2) * D + j] = w.z;
            Ws[(k + 3) * D + j] = w.w;
        }
    }
    // --- stage H directly (already K-major for our access) ---
    {
        const float4* H4  = reinterpret_cast<const float4*>(H);
        float4*       Hs4 = reinterpret_cast<float4*>(Hs);
        #pragma unroll
        for (int u = 0; u < 16; ++u)
            Hs4[u * 256 + tid] = H4[u * 256 + tid];
    }
    // --- stage h tile row-major (clamped for the final partial tile) ---
    {
        int i = tid >> 1, half = tid & 1;
        int row = row0 + i; if (row >= N) row = N - 1;
        const float4* hrow = reinterpret_cast<const float4*>(h + (size_t)row * D);
        float4*       Ar   = reinterpret_cast<float4*>(As + i * D);
        #pragma unroll
        for (int u = 0; u < 16; ++u)
            Ar[half * 16 + u] = hrow[half * 16 + u];
    }
    __syncthreads();

    const int tx = tid & 15;   // column group
    const int ty = tid >> 4;   // row group
    const int ro = ty * 8;
    const int co = tx * 8;

    unsigned long long acc[8][4];

    // ================= GEMM1: hp = h @ W^T + b =================
    #pragma unroll
    for (int ii = 0; ii < 8; ++ii)
        #pragma unroll
        for (int jj = 0; jj < 4; ++jj) acc[ii][jj] = 0ull;

    #pragma unroll 4
    for (int k = 0; k < D; ++k) {
        const ulonglong2* Bs = reinterpret_cast<const ulonglong2*>(Ws + k * D + co);
        ulonglong2 b01 = Bs[0], b23 = Bs[1];
        #pragma unroll
        for (int ii = 0; ii < 8; ++ii) {
            unsigned long long a2 = splat2(As[(ro + ii) * D + k]);
            ffma2(acc[ii][0], a2, b01.x);
            ffma2(acc[ii][1], a2, b01.y);
            ffma2(acc[ii][2], a2, b23.x);
            ffma2(acc[ii][3], a2, b23.y);
        }
    }
    // bias
    {
        const unsigned long long* bp =
            reinterpret_cast<const unsigned long long*>(Wb + co);
        unsigned long long bb0 = bp[0], bb1 = bp[1], bb2 = bp[2], bb3 = bp[3];
        #pragma unroll
        for (int ii = 0; ii < 8; ++ii) {
            fadd2(acc[ii][0], bb0);
            fadd2(acc[ii][1], bb1);
            fadd2(acc[ii][2], bb2);
            fadd2(acc[ii][3], bb3);
        }
    }

    __syncthreads();   // everyone done reading h tile from As

    // write hp: into As (for GEMM2) and to gmem (for edge gather)
    #pragma unroll
    for (int ii = 0; ii < 8; ++ii) {
        ulonglong2 p0 = make_ulonglong2(acc[ii][0], acc[ii][1]);
        ulonglong2 p1 = make_ulonglong2(acc[ii][2], acc[ii][3]);
        ulonglong2* sdst = reinterpret_cast<ulonglong2*>(As + (ro + ii) * D + co);
        sdst[0] = p0;
        sdst[1] = p1;
        int row = row0 + ro + ii;
        if (row < N) {
            ulonglong2* g = reinterpret_cast<ulonglong2*>(g_hp + (size_t)row * D + co);
            g[0] = p0;
            g[1] = p1;
        }
    }
    __syncthreads();

    // ================= GEMM2: hpH = hp @ H =================
    #pragma unroll
    for (int ii = 0; ii < 8; ++ii)
        #pragma unroll
        for (int jj = 0; jj < 4; ++jj) acc[ii][jj] = 0ull;

    #pragma unroll 4
    for (int k = 0; k < D; ++k) {
        const ulonglong2* Bs = reinterpret_cast<const ulonglong2*>(Hs + k * D + co);
        ulonglong2 b01 = Bs[0], b23 = Bs[1];
        #pragma unroll
        for (int ii = 0; ii < 8; ++ii) {
            unsigned long long a2 = splat2(As[(ro + ii) * D + k]);
            ffma2(acc[ii][0], a2, b01.x);
            ffma2(acc[ii][1], a2, b01.y);
            ffma2(acc[ii][2], a2, b23.x);
            ffma2(acc[ii][3], a2, b23.y);
        }
    }

    #pragma unroll
    for (int ii = 0; ii < 8; ++ii) {
        int row = row0 + ro + ii;
        if (row < N) {
            ulonglong2* g = reinterpret_cast<ulonglong2*>(g_hpH + (size_t)row * D + co);
            g[0] = make_ulonglong2(acc[ii][0], acc[ii][1]);
            g[1] = make_ulonglong2(acc[ii][2], acc[ii][3]);
        }
    }
}

// One warp per edge: lane i holds float4 slice i of both rows,
// squared-distance partial, shfl-xor reduce, lane 0 writes score.
// src/dst are int32 (the harness casts the reference's int64 indices down).
__global__ __launch_bounds__(256)
void edge_kernel(const int* __restrict__ src,
                 const int* __restrict__ dst,
                 float* __restrict__ out, int E, int N)
{
    int w    = (int)((blockIdx.x * blockDim.x + threadIdx.x) >> 5);
    int lane = threadIdx.x & 31;
    if (w >= E) return;

    int s = __ldg(src + w);
    int d = __ldg(dst + w);
    // defensive clamp: turns a dtype misread into a rel_err signal, not a crash
    s = min(max(s, 0), N - 1);
    d = min(max(d, 0), N - 1);

    const float4* a4 = reinterpret_cast<const float4*>(g_hp  + (size_t)s * D);
    const float4* b4 = reinterpret_cast<const float4*>(g_hpH + (size_t)d * D);
    float4 a = a4[lane];
    float4 b = b4[lane];

    float dx = a.x - b.x, dy = a.y - b.y, dz = a.z - b.z, dw = a.w - b.w;
    float sum = dx * dx + dy * dy + dz * dz + dw * dw;

    #pragma unroll
    for (int off = 16; off; off >>= 1)
        sum += __shfl_xor_sync(0xffffffffu, sum, off);

    if (lane == 0) out[w] = sum;
}

extern "C" void kernel_launch(void* const* d_in, const int* in_sizes, int n_in,
                              void* d_out, int out_size)
{
    const float* h   = (const float*)d_in[0];
    const int*   src = (const int*)d_in[1];
    const int*   dst = (const int*)d_in[2];
    const float* Ww  = (const float*)d_in[3];
    const float* Wb  = (const float*)d_in[4];
    const float* H   = (const float*)d_in[5];
    float*       out = (float*)d_out;

    int N = in_sizes[0] / D;
    if (N > NMAX) N = NMAX;
    int E = in_sizes[1];

    const int smem_bytes = 3 * D * D * (int)sizeof(float);  // 192 KB
    cudaFuncSetAttribute(node_transform_kernel,
                         cudaFuncAttributeMaxDynamicSharedMemorySize, smem_bytes);

    int nblocks = (N + BM - 1) / BM;
    node_transform_kernel<<<nblocks, 256, smem_bytes>>>(h, Ww, Wb, H, N);

    int eblocks = (E + 7) / 8;   // 8 warps (= 8 edges) per 256-thread block
    edge_kernel<<<eblocks, 256>>>(src, dst, out, E, N);
}

// round 10
// speedup vs baseline: 2.3321x; 2.3321x over previous
#include <cuda_runtime.h>
#include <cuda_fp16.h>
#include <cstdint>

#define D    128
#define BM   128
#define NMAX 100000
#define LDH  136   // padded row stride in halves (272B: conflict-free frags)

// fp16 node features for the edge gather (halves traffic; 51MB fits L2).
__device__ __half g_hp [(size_t)NMAX * D];
__device__ __half g_hpH[(size_t)NMAX * D];

__device__ __forceinline__ uint32_t h2u(__half2 v) {
    return *reinterpret_cast<uint32_t*>(&v);
}

__device__ __forceinline__ void mma16816(float* c,
                                         uint32_t a0, uint32_t a1,
                                         uint32_t a2, uint32_t a3,
                                         uint32_t b0, uint32_t b1) {
    asm volatile(
        "mma.sync.aligned.m16n8k16.row.col.f32.f16.f16.f32 "
        "{%0,%1,%2,%3}, {%4,%5,%6,%7}, {%8,%9}, {%0,%1,%2,%3};"
        : "+f"(c[0]), "+f"(c[1]), "+f"(c[2]), "+f"(c[3])
        : "r"(a0), "r"(a1), "r"(a2), "r"(a3), "r"(b0), "r"(b1));
}

// ============================================================================
// Node transform: hp = h@W^T + b ; hpH = hp@H.  fp16 HMMA, fp32 accumulate.
// 256 threads = 8 warps; warp w computes rows [16w, 16w+16) of the 128-row tile.
// GEMM1 accumulators feed GEMM2 A-fragments directly in registers.
// ============================================================================
__global__ __launch_bounds__(256, 1)
void node_kernel(const float* __restrict__ h,
                 const float* __restrict__ Ww,
                 const float* __restrict__ Wb,
                 const float* __restrict__ Hm,
                 int N)
{
    extern __shared__ char smem[];
    float*  bias = reinterpret_cast<float*>(smem);            // 512 B
    __half* As   = reinterpret_cast<__half*>(smem + 512);     // h tile   [128][LDH]
    __half* Ws   = As + 128 * LDH;                            // W        [128][LDH]
    __half* Hs   = Ws + 128 * LDH;                            // H^T      [128][LDH]

    const int tid  = threadIdx.x;
    const int row0 = blockIdx.x * BM;

    // ---- stage bias ----
    if (tid < 128) bias[tid] = Wb[tid];

    // ---- stage h tile and W (row = tid>>1, each thread covers 64 cols) ----
    {
        const int r  = tid >> 1;
        const int hf = tid & 1;
        int grow = row0 + r; if (grow >= N) grow = N - 1;
        const float4* hr = reinterpret_cast<const float4*>(h  + (size_t)grow * D);
        const float4* wr = reinterpret_cast<const float4*>(Ww + (size_t)r    * D);
        #pragma unroll 4
        for (int u = 0; u < 16; ++u) {
            int c = hf * 64 + u * 4;
            float4 v = hr[hf * 16 + u];
            uint2 p;
            p.x = h2u(__floats2half2_rn(v.x, v.y));
            p.y = h2u(__floats2half2_rn(v.z, v.w));
            *reinterpret_cast<uint2*>(&As[r * LDH + c]) = p;
            v = wr[hf * 16 + u];
            p.x = h2u(__floats2half2_rn(v.x, v.y));
            p.y = h2u(__floats2half2_rn(v.z, v.w));
            *reinterpret_cast<uint2*>(&Ws[r * LDH + c]) = p;
        }
    }
    // ---- stage H transposed: Hs[n][k] = H[k][n] (gmem reads coalesced over n) ----
    {
        const int n  = tid & 127;
        const int k0 = (tid >> 7) * 64;
        #pragma unroll 4
        for (int k = k0; k < k0 + 64; ++k)
            Hs[n * LDH + k] = __float2half_rn(Hm[k * D + n]);
    }
    __syncthreads();

    const int warp  = tid >> 5;
    const int lane  = tid & 31;
    const int qr    = lane >> 2;        // 0..7   (fragment row / B col)
    const int qc    = (lane & 3) * 2;   // 0,2,4,6 (fragment col / B row pair)
    const int rbase = warp * 16;

    float acc[16][4];
    #pragma unroll
    for (int nt = 0; nt < 16; ++nt)
        #pragma unroll
        for (int j = 0; j < 4; ++j) acc[nt][j] = 0.f;

    // ================= GEMM1: hp = h @ W^T =================
    #pragma unroll
    for (int ks = 0; ks < 8; ++ks) {
        const int kb = ks * 16;
        uint32_t a0 = *reinterpret_cast<const uint32_t*>(&As[(rbase + qr)     * LDH + kb + qc]);
        uint32_t a1 = *reinterpret_cast<const uint32_t*>(&As[(rbase + qr + 8) * LDH + kb + qc]);
        uint32_t a2 = *reinterpret_cast<const uint32_t*>(&As[(rbase + qr)     * LDH + kb + 8 + qc]);
        uint32_t a3 = *reinterpret_cast<const uint32_t*>(&As[(rbase + qr + 8) * LDH + kb + 8 + qc]);
        #pragma unroll
        for (int nt = 0; nt < 16; ++nt) {
            uint32_t b0 = *reinterpret_cast<const uint32_t*>(&Ws[(nt * 8 + qr) * LDH + kb + qc]);
            uint32_t b1 = *reinterpret_cast<const uint32_t*>(&Ws[(nt * 8 + qr) * LDH + kb + 8 + qc]);
            mma16816(acc[nt], a0, a1, a2, a3, b0, b1);
        }
    }

    // ---- epilogue 1: +bias, f16 pack (kept in regs for GEMM2), store g_hp ----
    uint32_t hp0[16], hp1[16];
    {
        const int r0g = row0 + rbase + qr;
        const int r1g = r0g + 8;
        #pragma unroll
        for (int nt = 0; nt < 16; ++nt) {
            const int c = nt * 8 + qc;
            float b0 = bias[c], b1 = bias[c + 1];
            hp0[nt] = h2u(__floats2half2_rn(acc[nt][0] + b0, acc[nt][1] + b1));
            hp1[nt] = h2u(__floats2half2_rn(acc[nt][2] + b0, acc[nt][3] + b1));
            if (r0g < N) *reinterpret_cast<uint32_t*>(&g_hp[(size_t)r0g * D + c]) = hp0[nt];
            if (r1g < N) *reinterpret_cast<uint32_t*>(&g_hp[(size_t)r1g * D + c]) = hp1[nt];
        }
    }

    // ================= GEMM2: hpH = hp @ H =================
    #pragma unroll
    for (int nt = 0; nt < 16; ++nt)
        #pragma unroll
        for (int j = 0; j < 4; ++j) acc[nt][j] = 0.f;

    #pragma unroll
    for (int ks = 0; ks < 8; ++ks) {
        const int kb = ks * 16;
        // A-fragments straight from GEMM1 results (same positional layout)
        uint32_t a0 = hp0[2 * ks];
        uint32_t a1 = hp1[2 * ks];
        uint32_t a2 = hp0[2 * ks + 1];
        uint32_t a3 = hp1[2 * ks + 1];
        #pragma unroll
        for (int nt = 0; nt < 16; ++nt) {
            uint32_t b0 = *reinterpret_cast<const uint32_t*>(&Hs[(nt * 8 + qr) * LDH + kb + qc]);
            uint32_t b1 = *reinterpret_cast<const uint32_t*>(&Hs[(nt * 8 + qr) * LDH + kb + 8 + qc]);
            mma16816(acc[nt], a0, a1, a2, a3, b0, b1);
        }
    }

    // ---- epilogue 2: f16, store g_hpH ----
    {
        const int r0g = row0 + rbase + qr;
        const int r1g = r0g + 8;
        #pragma unroll
        for (int nt = 0; nt < 16; ++nt) {
            const int c = nt * 8 + qc;
            uint32_t p0 = h2u(__floats2half2_rn(acc[nt][0], acc[nt][1]));
            uint32_t p1 = h2u(__floats2half2_rn(acc[nt][2], acc[nt][3]));
            if (r0g < N) *reinterpret_cast<uint32_t*>(&g_hpH[(size_t)r0g * D + c]) = p0;
            if (r1g < N) *reinterpret_cast<uint32_t*>(&g_hpH[(size_t)r1g * D + c]) = p1;
        }
    }
}

// ============================================================================
// Edge kernel: 2 edges per warp, 16 lanes x 16B per fp16 row.
// ============================================================================
__global__ __launch_bounds__(256)
void edge_kernel(const int* __restrict__ src,
                 const int* __restrict__ dst,
                 float* __restrict__ out, int E, int N)
{
    int gw   = (int)((blockIdx.x * blockDim.x + threadIdx.x) >> 5);
    int lane = threadIdx.x & 31;
    int e    = gw * 2 + (lane >> 4);
    if (e >= E) return;
    int slot = lane & 15;

    int s = __ldg(src + e);
    int d = __ldg(dst + e);
    s = min(max(s, 0), N - 1);
    d = min(max(d, 0), N - 1);

    uint4 a = reinterpret_cast<const uint4*>(g_hp  + (size_t)s * D)[slot];
    uint4 b = reinterpret_cast<const uint4*>(g_hpH + (size_t)d * D)[slot];

    const __half2* ah = reinterpret_cast<const __half2*>(&a);
    const __half2* bh = reinterpret_cast<const __half2*>(&b);
    float sum = 0.f;
    #pragma unroll
    for (int i = 0; i < 4; ++i) {
        float2 fa = __half22float2(ah[i]);
        float2 fb = __half22float2(bh[i]);
        float dx = fa.x - fb.x, dy = fa.y - fb.y;
        sum = fmaf(dx, dx, sum);
        sum = fmaf(dy, dy, sum);
    }
    #pragma unroll
    for (int off = 8; off; off >>= 1)
        sum += __shfl_xor_sync(0xffffffffu, sum, off);

    if (slot == 0) out[e] = sum;
}

extern "C" void kernel_launch(void* const* d_in, const int* in_sizes, int n_in,
                              void* d_out, int out_size)
{
    const float* h   = (const float*)d_in[0];
    const int*   src = (const int*)d_in[1];
    const int*   dst = (const int*)d_in[2];
    const float* Ww  = (const float*)d_in[3];
    const float* Wb  = (const float*)d_in[4];
    const float* Hm  = (const float*)d_in[5];
    float*       out = (float*)d_out;

    int N = in_sizes[0] / D;
    if (N > NMAX) N = NMAX;
    int E = in_sizes[1];

    const int smem_bytes = 512 + 3 * 128 * LDH * (int)sizeof(__half); // 104960 B
    cudaFuncSetAttribute(node_kernel,
                         cudaFuncAttributeMaxDynamicSharedMemorySize, smem_bytes);

    int nblocks = (N + BM - 1) / BM;
    node_kernel<<<nblocks, 256, smem_bytes>>>(h, Ww, Wb, Hm, N);

    int eblocks = (E / 2 + 7) / 8;   // 8 warps = 16 edges per block
    edge_kernel<<<eblocks, 256>>>(src, dst, out, E, N);
}